// round 14
// baseline (speedup 1.0000x reference)
#include <cuda_runtime.h>
#include <cuda_bf16.h>
#include <math.h>

// Problem constants
#define Bc   8
#define Sc   512
#define Dc   1024
#define Oc   1024
#define Tc   12
#define Lc   8
#define Mrows (Bc*Sc)          // 4096
#define NDEC 36                // T*DEP
#define NSPLIT 4               // split-K for uvg mma

typedef unsigned long long u64;
typedef unsigned int u32;

// ------------------------------------------------------------------
// Scratch (allocation-free: device globals)
// ------------------------------------------------------------------
__device__ float g_W2p[4][NDEC * Dc];       // K-split partials of W2^T
__device__ float g_bias2[NDEC];             // dW @ cb
__device__ __nv_bfloat16 g_Wh[96 * Dc];     // weight hi (bf16) [96][1024]
__device__ __nv_bfloat16 g_Wl[96 * Dc];     // weight lo (bf16)
__device__ float g_uvp[NSPLIT][Mrows * 96]; // split-K partials of uvg
__device__ float g_dec[Mrows * NDEC];       // sigmoid decision values

// ------------------------------------------------------------------
// helpers
// ------------------------------------------------------------------
__device__ __forceinline__ u64 pack2(float x, float y) {
    u64 r; asm("mov.b64 %0, {%1,%2};" : "=l"(r) : "f"(x), "f"(y)); return r;
}
__device__ __forceinline__ void unpack2(u64 v, float& x, float& y) {
    asm("mov.b64 {%0,%1}, %2;" : "=f"(x), "=f"(y) : "l"(v));
}
__device__ __forceinline__ void fma2(u64& d, u64 a, u64 b) {
    asm("fma.rn.f32x2 %0, %1, %2, %0;" : "+l"(d) : "l"(a), "l"(b));
}
__device__ __forceinline__ float softplusf(float v) {
    return (v > 20.f) ? v : log1pf(expf(v));
}
// sum of the 4 split-K partials at flat index idx
__device__ __forceinline__ float sum4(size_t idx) {
    return (g_uvp[0][idx] + g_uvp[1][idx]) + (g_uvp[2][idx] + g_uvp[3][idx]);
}
// float4 sum of the 4 split-K partials at float4-aligned flat index
__device__ __forceinline__ float4 sum4v(size_t fidx) {
    float4 a = *(const float4*)(g_uvp[0] + fidx);
    float4 b = *(const float4*)(g_uvp[1] + fidx);
    float4 c = *(const float4*)(g_uvp[2] + fidx);
    float4 d = *(const float4*)(g_uvp[3] + fidx);
    float4 r;
    r.x = (a.x + b.x) + (c.x + d.x);
    r.y = (a.y + b.y) + (c.y + d.y);
    r.z = (a.z + b.z) + (c.z + d.z);
    r.w = (a.w + b.w) + (c.w + d.w);
    return r;
}

// bf16 mma.sync (baseline PTX, works on sm_100)
__device__ __forceinline__ void mma_bf16(
    float& c0, float& c1, float& c2, float& c3,
    u32 a0, u32 a1, u32 a2, u32 a3, u32 b0, u32 b1)
{
    asm volatile(
        "mma.sync.aligned.m16n8k16.row.col.f32.bf16.bf16.f32 "
        "{%0,%1,%2,%3}, {%4,%5,%6,%7}, {%8,%9}, {%0,%1,%2,%3};"
        : "+f"(c0), "+f"(c1), "+f"(c2), "+f"(c3)
        : "r"(a0), "r"(a1), "r"(a2), "r"(a3), "r"(b0), "r"(b1));
}

__device__ __forceinline__ void bf16_split(float v, unsigned short& h, unsigned short& l) {
    __nv_bfloat16 hb = __float2bfloat16(v);
    float lo = v - __bfloat162float(hb);
    h = __bfloat16_as_ushort(hb);
    l = __bfloat16_as_ushort(__float2bfloat16(lo));
}

// ------------------------------------------------------------------
// K0a: W2^T partials.  W2p[part][tn][e] = sum_{d in part} cW[e][d]*dW[tn][d]
// ------------------------------------------------------------------
__global__ __launch_bounds__(256) void w2_partial(
    const float* __restrict__ cW, const float* __restrict__ dW)
{
    __shared__ float s_cWT[64][68];
    __shared__ float s_dW[NDEC][68];

    const int tid = threadIdx.x;
    const int e0  = blockIdx.x * 64;
    const int kb  = blockIdx.y * 256;
    const int el  = tid & 63;
    const int tg  = tid >> 6;

    float acc[9];
    #pragma unroll
    for (int j = 0; j < 9; ++j) acc[j] = 0.f;

    for (int ki = 0; ki < 4; ++ki) {
        const int k0 = kb + ki * 64;
        #pragma unroll
        for (int t = 0; t < 4; ++t) {
            int idx = tid + t * 256;
            int er = idx >> 4, cc = idx & 15;
            float4 v = *(const float4*)(cW + (size_t)(e0 + er) * Dc + k0 + cc * 4);
            s_cWT[cc * 4 + 0][er] = v.x;
            s_cWT[cc * 4 + 1][er] = v.y;
            s_cWT[cc * 4 + 2][er] = v.z;
            s_cWT[cc * 4 + 3][er] = v.w;
        }
        for (int idx = tid; idx < NDEC * 16; idx += 256) {
            int wr = idx >> 4, cc = idx & 15;
            float4 v = *(const float4*)(dW + (size_t)wr * Dc + k0 + cc * 4);
            s_dW[wr][cc * 4 + 0] = v.x;
            s_dW[wr][cc * 4 + 1] = v.y;
            s_dW[wr][cc * 4 + 2] = v.z;
            s_dW[wr][cc * 4 + 3] = v.w;
        }
        __syncthreads();

        #pragma unroll 4
        for (int kk = 0; kk < 64; ++kk) {
            float a = s_cWT[kk][el];
            #pragma unroll
            for (int j = 0; j < 9; ++j)
                acc[j] += a * s_dW[tg * 9 + j][kk];
        }
        __syncthreads();
    }

    #pragma unroll
    for (int j = 0; j < 9; ++j) {
        int tn = tg * 9 + j;
        g_W2p[blockIdx.y][(tn << 10) + e0 + el] = acc[j];
    }
}

// ------------------------------------------------------------------
// K0b (fused): blocks [0,96): bf16 hi/lo split of the 96x1024 weight
//   matrix; W2 reduction + gW transpose inline.
//   rows [0,36) dW | [36,72) sum W2p | [72,84) gW^T | [84,96) zero
// blocks [96,132): bias2[tn] = dot(cb, dW[tn])
// ------------------------------------------------------------------
__global__ __launch_bounds__(256) void wsplit_kernel(
    const float* __restrict__ dW, const float* __restrict__ gW,
    const float* __restrict__ cb)
{
    const int tid = threadIdx.x;

    if (blockIdx.x < 96) {
        int lin = blockIdx.x * 256 + tid;
        int c   = lin >> 8;
        int e4  = (lin & 255) * 4;
        float w[4];
        if (c < NDEC) {
            float4 v = *(const float4*)(dW + (size_t)c * Dc + e4);
            w[0] = v.x; w[1] = v.y; w[2] = v.z; w[3] = v.w;
        } else if (c < 72) {
            size_t o = (size_t)(c - 36) * Dc + e4;
            float4 a = *(const float4*)(g_W2p[0] + o);
            float4 b = *(const float4*)(g_W2p[1] + o);
            float4 cc = *(const float4*)(g_W2p[2] + o);
            float4 d = *(const float4*)(g_W2p[3] + o);
            w[0] = (a.x + b.x) + (cc.x + d.x);
            w[1] = (a.y + b.y) + (cc.y + d.y);
            w[2] = (a.z + b.z) + (cc.z + d.z);
            w[3] = (a.w + b.w) + (cc.w + d.w);
        } else if (c < 84) {
            int t = c - 72;
            #pragma unroll
            for (int j = 0; j < 4; ++j)
                w[j] = gW[(size_t)(e4 + j) * Tc + t];
        } else {
            w[0] = w[1] = w[2] = w[3] = 0.f;
        }
        unsigned short h[4], l[4];
        #pragma unroll
        for (int j = 0; j < 4; ++j) bf16_split(w[j], h[j], l[j]);
        u64 hw = (u64)h[0] | ((u64)h[1] << 16) | ((u64)h[2] << 32) | ((u64)h[3] << 48);
        u64 lw = (u64)l[0] | ((u64)l[1] << 16) | ((u64)l[2] << 32) | ((u64)l[3] << 48);
        *(u64*)((char*)g_Wh + ((size_t)c * Dc + e4) * 2) = hw;
        *(u64*)((char*)g_Wl + ((size_t)c * Dc + e4) * 2) = lw;
    } else {
        __shared__ float red[8];
        const int tn = blockIdx.x - 96;
        float4 c4 = ((const float4*)cb)[tid];
        float4 w4 = ((const float4*)(dW + (size_t)tn * Dc))[tid];
        float p = c4.x * w4.x + c4.y * w4.y + c4.z * w4.z + c4.w * w4.w;
        #pragma unroll
        for (int off = 16; off > 0; off >>= 1) p += __shfl_xor_sync(~0u, p, off);
        if ((tid & 31) == 0) red[tid >> 5] = p;
        __syncthreads();
        if (tid == 0) {
            float s = 0.f;
            #pragma unroll
            for (int wgi = 0; wgi < 8; ++wgi) s += red[wgi];
            g_bias2[tn] = s;
        }
    }
}

// ------------------------------------------------------------------
// K2: uvg = x @ W^T via mma.sync bf16 hi/lo (3 terms).
// grid (32 Mtiles, 4 Ksplit), 256 threads (8 warps = 4M x 2N).
// Block: 128 rows x 96 cols x K=256 slice (8 chunks of 32).
// ------------------------------------------------------------------
#define XW 20   // padded words per row

__global__ __launch_bounds__(256) void uvg_mma_kernel(const float* __restrict__ x)
{
    __shared__ u32 sXh[128][XW];
    __shared__ u32 sXl[128][XW];
    __shared__ u32 sWh[96][XW];
    __shared__ u32 sWl[96][XW];

    const int tid   = threadIdx.x;
    const int wid   = tid >> 5;
    const int lane  = tid & 31;
    const int row0  = blockIdx.x * 128;
    const int kbase = blockIdx.y * 256;

    const int wm = wid & 3;
    const int wn = wid >> 2;
    const int mbase = wm * 32;
    const int nbase = wn * 48;
    const int r  = lane >> 2;
    const int cq = lane & 3;

    float acc[2][6][4];
    #pragma unroll
    for (int mt = 0; mt < 2; ++mt)
        #pragma unroll
        for (int nt = 0; nt < 6; ++nt)
            #pragma unroll
            for (int e = 0; e < 4; ++e) acc[mt][nt][e] = 0.f;

    const int xk4  = tid & 7;
    const int wseg = tid & 7;

    float4 xv[4];
    uint2 wvh[3], wvl[3];

    // prefetch chunk 0
    {
        const int k0 = kbase;
        #pragma unroll
        for (int t = 0; t < 4; ++t) {
            int m = (tid + t * 256) >> 3;
            xv[t] = *(const float4*)(x + (size_t)(row0 + m) * Dc + k0 + xk4 * 4);
        }
        #pragma unroll
        for (int t = 0; t < 3; ++t) {
            int n = (tid + t * 256) >> 3;
            wvh[t] = *(const uint2*)((const char*)g_Wh + (size_t)n * 2048 + k0 * 2 + wseg * 8);
            wvl[t] = *(const uint2*)((const char*)g_Wl + (size_t)n * 2048 + k0 * 2 + wseg * 8);
        }
    }

    for (int ch = 0; ch < 8; ++ch) {
        // store current chunk
        #pragma unroll
        for (int t = 0; t < 4; ++t) {
            int m = (tid + t * 256) >> 3;
            float v[4] = {xv[t].x, xv[t].y, xv[t].z, xv[t].w};
            unsigned short h[4], l[4];
            #pragma unroll
            for (int e = 0; e < 4; ++e) bf16_split(v[e], h[e], l[e]);
            sXh[m][xk4 * 2 + 0] = ((u32)h[1] << 16) | h[0];
            sXh[m][xk4 * 2 + 1] = ((u32)h[3] << 16) | h[2];
            sXl[m][xk4 * 2 + 0] = ((u32)l[1] << 16) | l[0];
            sXl[m][xk4 * 2 + 1] = ((u32)l[3] << 16) | l[2];
        }
        #pragma unroll
        for (int t = 0; t < 3; ++t) {
            int n = (tid + t * 256) >> 3;
            sWh[n][wseg * 2 + 0] = wvh[t].x;
            sWh[n][wseg * 2 + 1] = wvh[t].y;
            sWl[n][wseg * 2 + 0] = wvl[t].x;
            sWl[n][wseg * 2 + 1] = wvl[t].y;
        }
        __syncthreads();

        // prefetch next chunk
        if (ch < 7) {
            const int k0 = kbase + (ch + 1) * 32;
            #pragma unroll
            for (int t = 0; t < 4; ++t) {
                int m = (tid + t * 256) >> 3;
                xv[t] = *(const float4*)(x + (size_t)(row0 + m) * Dc + k0 + xk4 * 4);
            }
            #pragma unroll
            for (int t = 0; t < 3; ++t) {
                int n = (tid + t * 256) >> 3;
                wvh[t] = *(const uint2*)((const char*)g_Wh + (size_t)n * 2048 + k0 * 2 + wseg * 8);
                wvl[t] = *(const uint2*)((const char*)g_Wl + (size_t)n * 2048 + k0 * 2 + wseg * 8);
            }
        }

        // compute: 2 k16 groups
        #pragma unroll
        for (int kg = 0; kg < 2; ++kg) {
            const int wb = kg * 8;
            u32 ah[2][4], al[2][4];
            #pragma unroll
            for (int mt = 0; mt < 2; ++mt) {
                const int ra = mbase + mt * 16 + r;
                ah[mt][0] = sXh[ra][wb + cq];
                ah[mt][1] = sXh[ra + 8][wb + cq];
                ah[mt][2] = sXh[ra][wb + cq + 4];
                ah[mt][3] = sXh[ra + 8][wb + cq + 4];
                al[mt][0] = sXl[ra][wb + cq];
                al[mt][1] = sXl[ra + 8][wb + cq];
                al[mt][2] = sXl[ra][wb + cq + 4];
                al[mt][3] = sXl[ra + 8][wb + cq + 4];
            }
            u32 bh[6][2], bl[6][2];
            #pragma unroll
            for (int nt = 0; nt < 6; ++nt) {
                const int n = nbase + nt * 8 + r;
                bh[nt][0] = sWh[n][wb + cq];
                bh[nt][1] = sWh[n][wb + cq + 4];
                bl[nt][0] = sWl[n][wb + cq];
                bl[nt][1] = sWl[n][wb + cq + 4];
            }
            #pragma unroll
            for (int mt = 0; mt < 2; ++mt)
                #pragma unroll
                for (int nt = 0; nt < 6; ++nt) {
                    float* c = acc[mt][nt];
                    mma_bf16(c[0], c[1], c[2], c[3],
                             ah[mt][0], ah[mt][1], ah[mt][2], ah[mt][3],
                             bh[nt][0], bh[nt][1]);
                    mma_bf16(c[0], c[1], c[2], c[3],
                             ah[mt][0], ah[mt][1], ah[mt][2], ah[mt][3],
                             bl[nt][0], bl[nt][1]);
                    mma_bf16(c[0], c[1], c[2], c[3],
                             al[mt][0], al[mt][1], al[mt][2], al[mt][3],
                             bh[nt][0], bh[nt][1]);
                }
        }
        __syncthreads();
    }

    float* dst = g_uvp[blockIdx.y];
    #pragma unroll
    for (int mt = 0; mt < 2; ++mt) {
        const int m = row0 + mbase + mt * 16;
        #pragma unroll
        for (int nt = 0; nt < 6; ++nt) {
            const int n = nbase + nt * 8 + cq * 2;
            *(float2*)(dst + (size_t)(m + r) * 96 + n)     = make_float2(acc[mt][nt][0], acc[mt][nt][1]);
            *(float2*)(dst + (size_t)(m + r + 8) * 96 + n) = make_float2(acc[mt][nt][2], acc[mt][nt][3]);
        }
    }
}

// ------------------------------------------------------------------
// K3: per-(b,tn) causal scan of u -> sigmoid decision values.
// grid (8 b, 3 tn-groups of 12), 384 threads = 12 tn x 32 chunks of 16.
// Bulk-stage u/v via float4 loads (cols 12g.. are 16B-aligned runs).
// DYNAMIC smem (52.8KB > 48KB static limit):
//   sU[512*12] | sV[512*12] | spw[512] | part[32*12]
// ------------------------------------------------------------------
#define SCAN_SMEM ((Sc * 12 + Sc * 12 + Sc + 32 * 12) * 4)

__global__ __launch_bounds__(384) void scan_kernel(
    const float* __restrict__ db, const float* __restrict__ ntl)
{
    extern __shared__ __align__(16) float dsm[];
    float* sU   = dsm;                    // [Sc][12]
    float* sV   = dsm + Sc * 12;          // [Sc][12]
    float* spw  = dsm + Sc * 24;          // [Sc]
    float* part = dsm + Sc * 24 + Sc;     // [32][12]

    const int tid = threadIdx.x;
    const int b   = blockIdx.x;
    const int tn0 = blockIdx.y * 12;

    // powers table (fp32)
    const float L2D = -0.15200309344504997f;   // log2(0.9)
    for (int i = tid; i < Sc; i += 384)
        spw[i] = exp2f((float)i * L2D);

    // bulk load: 512 rows x 3 float4 per array; 4 slots/thread/array
    #pragma unroll
    for (int it = 0; it < 4; ++it) {
        int idx = tid + it * 384;           // < 1536
        int s = idx / 3, q = idx % 3;
        size_t rbase = (size_t)(b * Sc + s) * 96;
        float4 uu = sum4v(rbase + 36 + tn0 + q * 4);
        float4 vv = sum4v(rbase + tn0 + q * 4);
        *(float4*)&sU[s * 12 + q * 4] = uu;
        *(float4*)&sV[s * 12 + q * 4] = vv;
    }
    __syncthreads();

    const int tl = tid % 12;           // local tn
    const int ch = tid / 12;           // 0..31
    const int s0 = ch * 16;
    const int tn = tn0 + tl;

    // pass 1: chunk partial sums of y_s = 0.9^s * u[b,s-1,tn]
    {
        float sum = 0.f;
        #pragma unroll
        for (int i = 0; i < 16; ++i) {
            int s = s0 + i;
            if (s >= 1) sum += sU[(s - 1) * 12 + tl] * spw[s];
        }
        part[ch * 12 + tl] = sum;
    }
    __syncthreads();

    if (tid < 12) {
        float run = 0.f;
        #pragma unroll
        for (int cch = 0; cch < 32; ++cch) {
            float t = part[cch * 12 + tid];
            part[cch * 12 + tid] = run;
            run += t;
        }
    }
    __syncthreads();

    // pass 2: emit sigmoid(z)
    {
        const float invT = 1.f / softplusf(ntl[tn] + 0.5413f);
        const float bias = db[tn] + g_bias2[tn];
        float C = part[ch * 12 + tl];
        #pragma unroll
        for (int i = 0; i < 16; ++i) {
            int s = s0 + i;
            int row = b * Sc + s;
            float pw = spw[s];
            if (s >= 1) C += sU[(s - 1) * 12 + tl] * pw;
            float recip = 1.0f / (pw + 1e-8f);
            float decE  = 0.1f * C * recip;
            float z     = (sV[s * 12 + tl] + decE + bias) * invT;
            g_dec[(size_t)row * NDEC + tn] = 1.f / (1.f + expf(-z));
        }
    }
}

// ------------------------------------------------------------------
// K5: fused q-construction + out = q @ leaf + LayerNorm
// 32 rows/block, 512 threads (2 cols each), 128 blocks; f32x2 FMAs.
// ------------------------------------------------------------------
__global__ __launch_bounds__(512) void out_ln_kernel(
    const float* __restrict__ leaf,
    const float* __restrict__ gb,
    const float* __restrict__ gamma,
    const float* __restrict__ beta,
    float* __restrict__ out)
{
    __shared__ __align__(16) float sQT[96][32];
    __shared__ float sRed[32][16][2];
    __shared__ float sMu[32], sRstd[32];

    const int tid  = threadIdx.x;
    const int row0 = blockIdx.x * 32;

    // phase 0: 384 threads, one per (row, tree)
    if (tid < 384) {
        const int row_l = tid / Tc;        // 0..31
        const int t     = tid % Tc;        // 0..11
        const int row   = row0 + row_l;

        float g[Tc];
        float mx = -1e30f;
        #pragma unroll
        for (int tt = 0; tt < Tc; ++tt) {
            g[tt] = sum4((size_t)row * 96 + 72 + tt) + gb[tt];
            mx = fmaxf(mx, g[tt]);
        }
        float sum = 0.f;
        #pragma unroll
        for (int tt = 0; tt < Tc; ++tt) { g[tt] = expf(g[tt] - mx); sum += g[tt]; }
        const float wt = g[t] / sum;

        const float d0 = g_dec[(size_t)row * NDEC + t * 3 + 0];
        const float d1 = g_dec[(size_t)row * NDEC + t * 3 + 1];
        const float d2 = g_dec[(size_t)row * NDEC + t * 3 + 2];
        #pragma unroll
        for (int l = 0; l < Lc; ++l) {
            float p = ((l & 4) ? (1.f - d0) : d0)
                    * ((l & 2) ? (1.f - d1) : d1)
                    * ((l & 1) ? (1.f - d2) : d2);
            sQT[t * 8 + l][row_l] = wt * p;
        }
    }
    __syncthreads();

    // GEMM: 32 rows x 2 cols per thread, f32x2 over row pairs
    const float2* leaf2 = (const float2*)leaf;
    u64 acc2[16][2];
    #pragma unroll
    for (int j = 0; j < 16; ++j) { acc2[j][0] = 0ull; acc2[j][1] = 0ull; }

    #pragma unroll 2
    for (int i = 0; i < 96; ++i) {
        float2 lf = leaf2[(size_t)i * 512 + tid];
        u64 lx = pack2(lf.x, lf.x);
        u64 ly = pack2(lf.y, lf.y);
        const ulonglong2* qp2 = (const ulonglong2*)&sQT[i][0];
        #pragma unroll
        for (int jj = 0; jj < 8; ++jj) {
            ulonglong2 qq = qp2[jj];
            fma2(acc2[2 * jj + 0][0], qq.x, lx);
            fma2(acc2[2 * jj + 0][1], qq.x, ly);
            fma2(acc2[2 * jj + 1][0], qq.y, lx);
            fma2(acc2[2 * jj + 1][1], qq.y, ly);
        }
    }

    float acc[32][2];
    #pragma unroll
    for (int j = 0; j < 16; ++j) {
        unpack2(acc2[j][0], acc[2 * j][0], acc[2 * j + 1][0]);
        unpack2(acc2[j][1], acc[2 * j][1], acc[2 * j + 1][1]);
    }

    const int wid  = tid >> 5;
    const int lane = tid & 31;
    #pragma unroll
    for (int r = 0; r < 32; ++r) {
        float s  = acc[r][0] + acc[r][1];
        float sq = acc[r][0] * acc[r][0] + acc[r][1] * acc[r][1];
        #pragma unroll
        for (int off = 16; off > 0; off >>= 1) {
            s  += __shfl_xor_sync(~0u, s,  off);
            sq += __shfl_xor_sync(~0u, sq, off);
        }
        if (lane == 0) { sRed[r][wid][0] = s; sRed[r][wid][1] = sq; }
    }
    __syncthreads();

    // each warp reduces 2 rows across the 16 warps
    {
        #pragma unroll
        for (int rr = 0; rr < 2; ++rr) {
            int r = wid * 2 + rr;
            float s  = (lane < 16) ? sRed[r][lane][0] : 0.f;
            float sq = (lane < 16) ? sRed[r][lane][1] : 0.f;
            #pragma unroll
            for (int off = 8; off > 0; off >>= 1) {
                s  += __shfl_xor_sync(~0u, s,  off);
                sq += __shfl_xor_sync(~0u, sq, off);
            }
            if (lane == 0) {
                float mu  = s * (1.f / Oc);
                float var = sq * (1.f / Oc) - mu * mu;
                sMu[r]   = mu;
                sRstd[r] = rsqrtf(var + 1e-5f);
            }
        }
    }
    __syncthreads();

    const float2 g2 = ((const float2*)gamma)[tid];
    const float2 b2 = ((const float2*)beta)[tid];
    float2* out2 = (float2*)out;
    #pragma unroll
    for (int r = 0; r < 32; ++r) {
        float mu = sMu[r], rstd = sRstd[r];
        float2 o;
        o.x = (acc[r][0] - mu) * rstd * g2.x + b2.x;
        o.y = (acc[r][1] - mu) * rstd * g2.y + b2.y;
        out2[(size_t)(row0 + r) * 512 + tid] = o;
    }
}

// ------------------------------------------------------------------
// launch
// ------------------------------------------------------------------
extern "C" void kernel_launch(void* const* d_in, const int* in_sizes, int n_in,
                              void* d_out, int out_size)
{
    const float* x     = (const float*)d_in[0];
    const float* cW    = (const float*)d_in[1];
    const float* cb    = (const float*)d_in[2];
    const float* dW    = (const float*)d_in[3];
    const float* db    = (const float*)d_in[4];
    const float* leaf  = (const float*)d_in[5];
    const float* gW    = (const float*)d_in[6];
    const float* gb    = (const float*)d_in[7];
    const float* ntl   = (const float*)d_in[8];
    const float* gamma = (const float*)d_in[9];
    const float* beta  = (const float*)d_in[10];
    float* out = (float*)d_out;

    static bool attr_done = false;
    if (!attr_done) {
        cudaFuncSetAttribute(scan_kernel,
                             cudaFuncAttributeMaxDynamicSharedMemorySize, SCAN_SMEM);
        attr_done = true;
    }

    w2_partial<<<dim3(16, 4), 256>>>(cW, dW);
    wsplit_kernel<<<96 + NDEC, 256>>>(dW, gW, cb);
    uvg_mma_kernel<<<dim3(32, NSPLIT), 256>>>(x);
    scan_kernel<<<dim3(Bc, 3), 384, SCAN_SMEM>>>(db, ntl);
    out_ln_kernel<<<Mrows / 32, 512>>>(leaf, gb, gamma, beta, out);
}

// round 16
// speedup vs baseline: 1.0777x; 1.0777x over previous
#include <cuda_runtime.h>
#include <cuda_bf16.h>
#include <math.h>

// Problem constants
#define Bc   8
#define Sc   512
#define Dc   1024
#define Oc   1024
#define Tc   12
#define Lc   8
#define Mrows (Bc*Sc)          // 4096
#define NDEC 36                // T*DEP
#define NSPLIT 4               // split-K for uvg mma

typedef unsigned long long u64;
typedef unsigned int u32;

// ------------------------------------------------------------------
// Scratch (allocation-free: device globals)
// ------------------------------------------------------------------
__device__ float g_W2p[4][NDEC * Dc];       // K-split partials of W2^T
__device__ float g_bias2[NDEC];             // dW @ cb
__device__ __nv_bfloat16 g_Wh[96 * Dc];     // weight hi (bf16) [96][1024]
__device__ __nv_bfloat16 g_Wl[96 * Dc];     // weight lo (bf16)
__device__ float g_uvp[NSPLIT][Mrows * 96]; // split-K partials of uvg
__device__ float g_dec[Mrows * NDEC];       // sigmoid decision values

// ------------------------------------------------------------------
// helpers
// ------------------------------------------------------------------
__device__ __forceinline__ u64 pack2(float x, float y) {
    u64 r; asm("mov.b64 %0, {%1,%2};" : "=l"(r) : "f"(x), "f"(y)); return r;
}
__device__ __forceinline__ void unpack2(u64 v, float& x, float& y) {
    asm("mov.b64 {%0,%1}, %2;" : "=f"(x), "=f"(y) : "l"(v));
}
__device__ __forceinline__ void fma2(u64& d, u64 a, u64 b) {
    asm("fma.rn.f32x2 %0, %1, %2, %0;" : "+l"(d) : "l"(a), "l"(b));
}
__device__ __forceinline__ float softplusf(float v) {
    return (v > 20.f) ? v : log1pf(expf(v));
}
__device__ __forceinline__ u32 smem_u32(const void* p) {
    u32 a;
    asm("{ .reg .u64 t; cvta.to.shared.u64 t, %1; cvt.u32.u64 %0, t; }"
        : "=r"(a) : "l"(p));
    return a;
}
__device__ __forceinline__ void cp_async16(u32 dst_smem, const void* src) {
    asm volatile("cp.async.cg.shared.global [%0], [%1], 16;"
                 :: "r"(dst_smem), "l"(src) : "memory");
}
#define CP_COMMIT() asm volatile("cp.async.commit_group;" ::: "memory")
#define CP_WAIT0()  asm volatile("cp.async.wait_group 0;" ::: "memory")

// sum of the 4 split-K partials at flat index idx
__device__ __forceinline__ float sum4(size_t idx) {
    return (g_uvp[0][idx] + g_uvp[1][idx]) + (g_uvp[2][idx] + g_uvp[3][idx]);
}

// bf16 mma.sync (baseline PTX, works on sm_100)
__device__ __forceinline__ void mma_bf16(
    float& c0, float& c1, float& c2, float& c3,
    u32 a0, u32 a1, u32 a2, u32 a3, u32 b0, u32 b1)
{
    asm volatile(
        "mma.sync.aligned.m16n8k16.row.col.f32.bf16.bf16.f32 "
        "{%0,%1,%2,%3}, {%4,%5,%6,%7}, {%8,%9}, {%0,%1,%2,%3};"
        : "+f"(c0), "+f"(c1), "+f"(c2), "+f"(c3)
        : "r"(a0), "r"(a1), "r"(a2), "r"(a3), "r"(b0), "r"(b1));
}

__device__ __forceinline__ void bf16_split(float v, unsigned short& h, unsigned short& l) {
    __nv_bfloat16 hb = __float2bfloat16(v);
    float lo = v - __bfloat162float(hb);
    h = __bfloat16_as_ushort(hb);
    l = __bfloat16_as_ushort(__float2bfloat16(lo));
}

// ------------------------------------------------------------------
// K0a: W2^T partials.  W2p[part][tn][e] = sum_{d in part} cW[e][d]*dW[tn][d]
// ------------------------------------------------------------------
__global__ __launch_bounds__(256) void w2_partial(
    const float* __restrict__ cW, const float* __restrict__ dW)
{
    __shared__ float s_cWT[64][68];
    __shared__ float s_dW[NDEC][68];

    const int tid = threadIdx.x;
    const int e0  = blockIdx.x * 64;
    const int kb  = blockIdx.y * 256;
    const int el  = tid & 63;
    const int tg  = tid >> 6;

    float acc[9];
    #pragma unroll
    for (int j = 0; j < 9; ++j) acc[j] = 0.f;

    for (int ki = 0; ki < 4; ++ki) {
        const int k0 = kb + ki * 64;
        #pragma unroll
        for (int t = 0; t < 4; ++t) {
            int idx = tid + t * 256;
            int er = idx >> 4, cc = idx & 15;
            float4 v = *(const float4*)(cW + (size_t)(e0 + er) * Dc + k0 + cc * 4);
            s_cWT[cc * 4 + 0][er] = v.x;
            s_cWT[cc * 4 + 1][er] = v.y;
            s_cWT[cc * 4 + 2][er] = v.z;
            s_cWT[cc * 4 + 3][er] = v.w;
        }
        for (int idx = tid; idx < NDEC * 16; idx += 256) {
            int wr = idx >> 4, cc = idx & 15;
            float4 v = *(const float4*)(dW + (size_t)wr * Dc + k0 + cc * 4);
            s_dW[wr][cc * 4 + 0] = v.x;
            s_dW[wr][cc * 4 + 1] = v.y;
            s_dW[wr][cc * 4 + 2] = v.z;
            s_dW[wr][cc * 4 + 3] = v.w;
        }
        __syncthreads();

        #pragma unroll 4
        for (int kk = 0; kk < 64; ++kk) {
            float a = s_cWT[kk][el];
            #pragma unroll
            for (int j = 0; j < 9; ++j)
                acc[j] += a * s_dW[tg * 9 + j][kk];
        }
        __syncthreads();
    }

    #pragma unroll
    for (int j = 0; j < 9; ++j) {
        int tn = tg * 9 + j;
        g_W2p[blockIdx.y][(tn << 10) + e0 + el] = acc[j];
    }
}

// ------------------------------------------------------------------
// K0b (fused): blocks [0,96): bf16 hi/lo split of the 96x1024 weight
//   matrix; W2 reduction + gW transpose inline.
// blocks [96,132): bias2[tn] = dot(cb, dW[tn])
// ------------------------------------------------------------------
__global__ __launch_bounds__(256) void wsplit_kernel(
    const float* __restrict__ dW, const float* __restrict__ gW,
    const float* __restrict__ cb)
{
    const int tid = threadIdx.x;

    if (blockIdx.x < 96) {
        int lin = blockIdx.x * 256 + tid;
        int c   = lin >> 8;
        int e4  = (lin & 255) * 4;
        float w[4];
        if (c < NDEC) {
            float4 v = *(const float4*)(dW + (size_t)c * Dc + e4);
            w[0] = v.x; w[1] = v.y; w[2] = v.z; w[3] = v.w;
        } else if (c < 72) {
            size_t o = (size_t)(c - 36) * Dc + e4;
            float4 a = *(const float4*)(g_W2p[0] + o);
            float4 b = *(const float4*)(g_W2p[1] + o);
            float4 cc = *(const float4*)(g_W2p[2] + o);
            float4 d = *(const float4*)(g_W2p[3] + o);
            w[0] = (a.x + b.x) + (cc.x + d.x);
            w[1] = (a.y + b.y) + (cc.y + d.y);
            w[2] = (a.z + b.z) + (cc.z + d.z);
            w[3] = (a.w + b.w) + (cc.w + d.w);
        } else if (c < 84) {
            int t = c - 72;
            #pragma unroll
            for (int j = 0; j < 4; ++j)
                w[j] = gW[(size_t)(e4 + j) * Tc + t];
        } else {
            w[0] = w[1] = w[2] = w[3] = 0.f;
        }
        unsigned short h[4], l[4];
        #pragma unroll
        for (int j = 0; j < 4; ++j) bf16_split(w[j], h[j], l[j]);
        u64 hw = (u64)h[0] | ((u64)h[1] << 16) | ((u64)h[2] << 32) | ((u64)h[3] << 48);
        u64 lw = (u64)l[0] | ((u64)l[1] << 16) | ((u64)l[2] << 32) | ((u64)l[3] << 48);
        *(u64*)((char*)g_Wh + ((size_t)c * Dc + e4) * 2) = hw;
        *(u64*)((char*)g_Wl + ((size_t)c * Dc + e4) * 2) = lw;
    } else {
        __shared__ float red[8];
        const int tn = blockIdx.x - 96;
        float4 c4 = ((const float4*)cb)[tid];
        float4 w4 = ((const float4*)(dW + (size_t)tn * Dc))[tid];
        float p = c4.x * w4.x + c4.y * w4.y + c4.z * w4.z + c4.w * w4.w;
        #pragma unroll
        for (int off = 16; off > 0; off >>= 1) p += __shfl_xor_sync(~0u, p, off);
        if ((tid & 31) == 0) red[tid >> 5] = p;
        __syncthreads();
        if (tid == 0) {
            float s = 0.f;
            #pragma unroll
            for (int wgi = 0; wgi < 8; ++wgi) s += red[wgi];
            g_bias2[tn] = s;
        }
    }
}

// ------------------------------------------------------------------
// K2: uvg = x @ W^T via mma.sync bf16 hi/lo (3 terms).
// grid (32 Mtiles, 4 Ksplit), 256 threads (8 warps = 4M x 2N).
// ------------------------------------------------------------------
#define XW 20   // padded words per row

__global__ __launch_bounds__(256) void uvg_mma_kernel(const float* __restrict__ x)
{
    __shared__ u32 sXh[128][XW];
    __shared__ u32 sXl[128][XW];
    __shared__ u32 sWh[96][XW];
    __shared__ u32 sWl[96][XW];

    const int tid   = threadIdx.x;
    const int wid   = tid >> 5;
    const int lane  = tid & 31;
    const int row0  = blockIdx.x * 128;
    const int kbase = blockIdx.y * 256;

    const int wm = wid & 3;
    const int wn = wid >> 2;
    const int mbase = wm * 32;
    const int nbase = wn * 48;
    const int r  = lane >> 2;
    const int cq = lane & 3;

    float acc[2][6][4];
    #pragma unroll
    for (int mt = 0; mt < 2; ++mt)
        #pragma unroll
        for (int nt = 0; nt < 6; ++nt)
            #pragma unroll
            for (int e = 0; e < 4; ++e) acc[mt][nt][e] = 0.f;

    const int xk4  = tid & 7;
    const int wseg = tid & 7;

    float4 xv[4];
    uint2 wvh[3], wvl[3];

    {
        const int k0 = kbase;
        #pragma unroll
        for (int t = 0; t < 4; ++t) {
            int m = (tid + t * 256) >> 3;
            xv[t] = *(const float4*)(x + (size_t)(row0 + m) * Dc + k0 + xk4 * 4);
        }
        #pragma unroll
        for (int t = 0; t < 3; ++t) {
            int n = (tid + t * 256) >> 3;
            wvh[t] = *(const uint2*)((const char*)g_Wh + (size_t)n * 2048 + k0 * 2 + wseg * 8);
            wvl[t] = *(const uint2*)((const char*)g_Wl + (size_t)n * 2048 + k0 * 2 + wseg * 8);
        }
    }

    for (int ch = 0; ch < 8; ++ch) {
        #pragma unroll
        for (int t = 0; t < 4; ++t) {
            int m = (tid + t * 256) >> 3;
            float v[4] = {xv[t].x, xv[t].y, xv[t].z, xv[t].w};
            unsigned short h[4], l[4];
            #pragma unroll
            for (int e = 0; e < 4; ++e) bf16_split(v[e], h[e], l[e]);
            sXh[m][xk4 * 2 + 0] = ((u32)h[1] << 16) | h[0];
            sXh[m][xk4 * 2 + 1] = ((u32)h[3] << 16) | h[2];
            sXl[m][xk4 * 2 + 0] = ((u32)l[1] << 16) | l[0];
            sXl[m][xk4 * 2 + 1] = ((u32)l[3] << 16) | l[2];
        }
        #pragma unroll
        for (int t = 0; t < 3; ++t) {
            int n = (tid + t * 256) >> 3;
            sWh[n][wseg * 2 + 0] = wvh[t].x;
            sWh[n][wseg * 2 + 1] = wvh[t].y;
            sWl[n][wseg * 2 + 0] = wvl[t].x;
            sWl[n][wseg * 2 + 1] = wvl[t].y;
        }
        __syncthreads();

        if (ch < 7) {
            const int k0 = kbase + (ch + 1) * 32;
            #pragma unroll
            for (int t = 0; t < 4; ++t) {
                int m = (tid + t * 256) >> 3;
                xv[t] = *(const float4*)(x + (size_t)(row0 + m) * Dc + k0 + xk4 * 4);
            }
            #pragma unroll
            for (int t = 0; t < 3; ++t) {
                int n = (tid + t * 256) >> 3;
                wvh[t] = *(const uint2*)((const char*)g_Wh + (size_t)n * 2048 + k0 * 2 + wseg * 8);
                wvl[t] = *(const uint2*)((const char*)g_Wl + (size_t)n * 2048 + k0 * 2 + wseg * 8);
            }
        }

        #pragma unroll
        for (int kg = 0; kg < 2; ++kg) {
            const int wb = kg * 8;
            u32 ah[2][4], al[2][4];
            #pragma unroll
            for (int mt = 0; mt < 2; ++mt) {
                const int ra = mbase + mt * 16 + r;
                ah[mt][0] = sXh[ra][wb + cq];
                ah[mt][1] = sXh[ra + 8][wb + cq];
                ah[mt][2] = sXh[ra][wb + cq + 4];
                ah[mt][3] = sXh[ra + 8][wb + cq + 4];
                al[mt][0] = sXl[ra][wb + cq];
                al[mt][1] = sXl[ra + 8][wb + cq];
                al[mt][2] = sXl[ra][wb + cq + 4];
                al[mt][3] = sXl[ra + 8][wb + cq + 4];
            }
            u32 bh[6][2], bl[6][2];
            #pragma unroll
            for (int nt = 0; nt < 6; ++nt) {
                const int n = nbase + nt * 8 + r;
                bh[nt][0] = sWh[n][wb + cq];
                bh[nt][1] = sWh[n][wb + cq + 4];
                bl[nt][0] = sWl[n][wb + cq];
                bl[nt][1] = sWl[n][wb + cq + 4];
            }
            #pragma unroll
            for (int mt = 0; mt < 2; ++mt)
                #pragma unroll
                for (int nt = 0; nt < 6; ++nt) {
                    float* c = acc[mt][nt];
                    mma_bf16(c[0], c[1], c[2], c[3],
                             ah[mt][0], ah[mt][1], ah[mt][2], ah[mt][3],
                             bh[nt][0], bh[nt][1]);
                    mma_bf16(c[0], c[1], c[2], c[3],
                             ah[mt][0], ah[mt][1], ah[mt][2], ah[mt][3],
                             bl[nt][0], bl[nt][1]);
                    mma_bf16(c[0], c[1], c[2], c[3],
                             al[mt][0], al[mt][1], al[mt][2], al[mt][3],
                             bh[nt][0], bh[nt][1]);
                }
        }
        __syncthreads();
    }

    float* dst = g_uvp[blockIdx.y];
    #pragma unroll
    for (int mt = 0; mt < 2; ++mt) {
        const int m = row0 + mbase + mt * 16;
        #pragma unroll
        for (int nt = 0; nt < 6; ++nt) {
            const int n = nbase + nt * 8 + cq * 2;
            *(float2*)(dst + (size_t)(m + r) * 96 + n)     = make_float2(acc[mt][nt][0], acc[mt][nt][1]);
            *(float2*)(dst + (size_t)(m + r + 8) * 96 + n) = make_float2(acc[mt][nt][2], acc[mt][nt][3]);
        }
    }
}

// ------------------------------------------------------------------
// K3: per-(b,tn) causal scan of u -> sigmoid decision values.
// grid (8 b, 3 tn-groups of 12), 384 threads = 12 tn x 32 chunks of 16.
// cp.async stages ALL 4 splits raw into smem (no payload registers,
// full-rate issue), then float4 in-smem reduce, then the two passes.
// dyn smem: stage[4][12288] | spw[512] | part[384]  = 195.5 KB
// ------------------------------------------------------------------
#define SCAN_STAGE  12288                       // floats per split (u 6144 + v 6144)
#define SCAN_SMEM   ((4 * SCAN_STAGE + Sc + 384) * 4)

__global__ __launch_bounds__(384) void scan_kernel(
    const float* __restrict__ db, const float* __restrict__ ntl)
{
    extern __shared__ __align__(16) float dsm[];
    float* sU   = dsm;                          // [Sc][12] after reduce
    float* sV   = dsm + 6144;                   // [Sc][12] after reduce
    float* spw  = dsm + 4 * SCAN_STAGE;         // [Sc]
    float* part = dsm + 4 * SCAN_STAGE + Sc;    // [32][12]

    const int tid = threadIdx.x;
    const int b   = blockIdx.x;
    const int tn0 = blockIdx.y * 12;
    const u32 smem_base = smem_u32(dsm);

    // issue all cp.async copies: 12288 x 16B, 32 per thread
    #pragma unroll
    for (int it = 0; it < 32; ++it) {
        int cid = tid + it * 384;               // < 12288
        int k   = cid / 3072;
        int rem = cid - k * 3072;
        int s   = rem / 6;
        int j   = rem - s * 6;
        const float* src;
        int dstf;
        if (j < 3) {
            src  = g_uvp[k] + (size_t)(b * Sc + s) * 96 + 36 + tn0 + j * 4;
            dstf = k * SCAN_STAGE + s * 12 + j * 4;
        } else {
            src  = g_uvp[k] + (size_t)(b * Sc + s) * 96 + tn0 + (j - 3) * 4;
            dstf = k * SCAN_STAGE + 6144 + s * 12 + (j - 3) * 4;
        }
        cp_async16(smem_base + dstf * 4, src);
    }
    CP_COMMIT();

    // overlap: powers table (fp32)
    const float L2D = -0.15200309344504997f;    // log2(0.9)
    for (int i = tid; i < Sc; i += 384)
        spw[i] = exp2f((float)i * L2D);

    CP_WAIT0();
    __syncthreads();

    // in-place reduce of 4 splits (same order as sum4: (s0+s1)+(s2+s3))
    #pragma unroll
    for (int it = 0; it < 8; ++it) {
        int i4 = (tid + it * 384) * 4;          // 3072 float4 total
        float4 a = *(float4*)&dsm[i4];
        float4 p1 = *(float4*)&dsm[SCAN_STAGE + i4];
        float4 p2 = *(float4*)&dsm[2 * SCAN_STAGE + i4];
        float4 p3 = *(float4*)&dsm[3 * SCAN_STAGE + i4];
        a.x = (a.x + p1.x) + (p2.x + p3.x);
        a.y = (a.y + p1.y) + (p2.y + p3.y);
        a.z = (a.z + p1.z) + (p2.z + p3.z);
        a.w = (a.w + p1.w) + (p2.w + p3.w);
        *(float4*)&dsm[i4] = a;
    }
    __syncthreads();

    const int tl = tid % 12;           // local tn
    const int ch = tid / 12;           // 0..31
    const int s0 = ch * 16;
    const int tn = tn0 + tl;

    // pass 1: chunk partial sums of y_s = 0.9^s * u[b,s-1,tn]
    {
        float sum = 0.f;
        #pragma unroll
        for (int i = 0; i < 16; ++i) {
            int s = s0 + i;
            if (s >= 1) sum += sU[(s - 1) * 12 + tl] * spw[s];
        }
        part[ch * 12 + tl] = sum;
    }
    __syncthreads();

    if (tid < 12) {
        float run = 0.f;
        #pragma unroll
        for (int cch = 0; cch < 32; ++cch) {
            float t = part[cch * 12 + tid];
            part[cch * 12 + tid] = run;
            run += t;
        }
    }
    __syncthreads();

    // pass 2: emit sigmoid(z)
    {
        const float invT = 1.f / softplusf(ntl[tn] + 0.5413f);
        const float bias = db[tn] + g_bias2[tn];
        float C = part[ch * 12 + tl];
        #pragma unroll
        for (int i = 0; i < 16; ++i) {
            int s = s0 + i;
            int row = b * Sc + s;
            float pw = spw[s];
            if (s >= 1) C += sU[(s - 1) * 12 + tl] * pw;
            float recip = 1.0f / (pw + 1e-8f);
            float decE  = 0.1f * C * recip;
            float z     = (sV[s * 12 + tl] + decE + bias) * invT;
            g_dec[(size_t)row * NDEC + tn] = 1.f / (1.f + expf(-z));
        }
    }
}

// ------------------------------------------------------------------
// K5: fused q-construction + out = q @ leaf + LayerNorm
// 32 rows/block, 512 threads (2 cols each), 128 blocks; f32x2 FMAs.
// ------------------------------------------------------------------
__global__ __launch_bounds__(512) void out_ln_kernel(
    const float* __restrict__ leaf,
    const float* __restrict__ gb,
    const float* __restrict__ gamma,
    const float* __restrict__ beta,
    float* __restrict__ out)
{
    __shared__ __align__(16) float sQT[96][32];
    __shared__ float sRed[32][16][2];
    __shared__ float sMu[32], sRstd[32];

    const int tid  = threadIdx.x;
    const int row0 = blockIdx.x * 32;

    // phase 0: 384 threads, one per (row, tree)
    if (tid < 384) {
        const int row_l = tid / Tc;        // 0..31
        const int t     = tid % Tc;        // 0..11
        const int row   = row0 + row_l;

        float g[Tc];
        float mx = -1e30f;
        #pragma unroll
        for (int tt = 0; tt < Tc; ++tt) {
            g[tt] = sum4((size_t)row * 96 + 72 + tt) + gb[tt];
            mx = fmaxf(mx, g[tt]);
        }
        float sum = 0.f;
        #pragma unroll
        for (int tt = 0; tt < Tc; ++tt) { g[tt] = expf(g[tt] - mx); sum += g[tt]; }
        const float wt = g[t] / sum;

        const float d0 = g_dec[(size_t)row * NDEC + t * 3 + 0];
        const float d1 = g_dec[(size_t)row * NDEC + t * 3 + 1];
        const float d2 = g_dec[(size_t)row * NDEC + t * 3 + 2];
        #pragma unroll
        for (int l = 0; l < Lc; ++l) {
            float p = ((l & 4) ? (1.f - d0) : d0)
                    * ((l & 2) ? (1.f - d1) : d1)
                    * ((l & 1) ? (1.f - d2) : d2);
            sQT[t * 8 + l][row_l] = wt * p;
        }
    }
    __syncthreads();

    // GEMM: 32 rows x 2 cols per thread, f32x2 over row pairs
    const float2* leaf2 = (const float2*)leaf;
    u64 acc2[16][2];
    #pragma unroll
    for (int j = 0; j < 16; ++j) { acc2[j][0] = 0ull; acc2[j][1] = 0ull; }

    #pragma unroll 2
    for (int i = 0; i < 96; ++i) {
        float2 lf = leaf2[(size_t)i * 512 + tid];
        u64 lx = pack2(lf.x, lf.x);
        u64 ly = pack2(lf.y, lf.y);
        const ulonglong2* qp2 = (const ulonglong2*)&sQT[i][0];
        #pragma unroll
        for (int jj = 0; jj < 8; ++jj) {
            ulonglong2 qq = qp2[jj];
            fma2(acc2[2 * jj + 0][0], qq.x, lx);
            fma2(acc2[2 * jj + 0][1], qq.x, ly);
            fma2(acc2[2 * jj + 1][0], qq.y, lx);
            fma2(acc2[2 * jj + 1][1], qq.y, ly);
        }
    }

    float acc[32][2];
    #pragma unroll
    for (int j = 0; j < 16; ++j) {
        unpack2(acc2[j][0], acc[2 * j][0], acc[2 * j + 1][0]);
        unpack2(acc2[j][1], acc[2 * j][1], acc[2 * j + 1][1]);
    }

    const int wid  = tid >> 5;
    const int lane = tid & 31;
    #pragma unroll
    for (int r = 0; r < 32; ++r) {
        float s  = acc[r][0] + acc[r][1];
        float sq = acc[r][0] * acc[r][0] + acc[r][1] * acc[r][1];
        #pragma unroll
        for (int off = 16; off > 0; off >>= 1) {
            s  += __shfl_xor_sync(~0u, s,  off);
            sq += __shfl_xor_sync(~0u, sq, off);
        }
        if (lane == 0) { sRed[r][wid][0] = s; sRed[r][wid][1] = sq; }
    }
    __syncthreads();

    // each warp reduces 2 rows across the 16 warps
    {
        #pragma unroll
        for (int rr = 0; rr < 2; ++rr) {
            int r = wid * 2 + rr;
            float s  = (lane < 16) ? sRed[r][lane][0] : 0.f;
            float sq = (lane < 16) ? sRed[r][lane][1] : 0.f;
            #pragma unroll
            for (int off = 8; off > 0; off >>= 1) {
                s  += __shfl_xor_sync(~0u, s,  off);
                sq += __shfl_xor_sync(~0u, sq, off);
            }
            if (lane == 0) {
                float mu  = s * (1.f / Oc);
                float var = sq * (1.f / Oc) - mu * mu;
                sMu[r]   = mu;
                sRstd[r] = rsqrtf(var + 1e-5f);
            }
        }
    }
    __syncthreads();

    const float2 g2 = ((const float2*)gamma)[tid];
    const float2 b2 = ((const float2*)beta)[tid];
    float2* out2 = (float2*)out;
    #pragma unroll
    for (int r = 0; r < 32; ++r) {
        float mu = sMu[r], rstd = sRstd[r];
        float2 o;
        o.x = (acc[r][0] - mu) * rstd * g2.x + b2.x;
        o.y = (acc[r][1] - mu) * rstd * g2.y + b2.y;
        out2[(size_t)(row0 + r) * 512 + tid] = o;
    }
}

// ------------------------------------------------------------------
// launch
// ------------------------------------------------------------------
extern "C" void kernel_launch(void* const* d_in, const int* in_sizes, int n_in,
                              void* d_out, int out_size)
{
    const float* x     = (const float*)d_in[0];
    const float* cW    = (const float*)d_in[1];
    const float* cb    = (const float*)d_in[2];
    const float* dW    = (const float*)d_in[3];
    const float* db    = (const float*)d_in[4];
    const float* leaf  = (const float*)d_in[5];
    const float* gW    = (const float*)d_in[6];
    const float* gb    = (const float*)d_in[7];
    const float* ntl   = (const float*)d_in[8];
    const float* gamma = (const float*)d_in[9];
    const float* beta  = (const float*)d_in[10];
    float* out = (float*)d_out;

    static bool attr_done = false;
    if (!attr_done) {
        cudaFuncSetAttribute(scan_kernel,
                             cudaFuncAttributeMaxDynamicSharedMemorySize, SCAN_SMEM);
        attr_done = true;
    }

    w2_partial<<<dim3(16, 4), 256>>>(cW, dW);
    wsplit_kernel<<<96 + NDEC, 256>>>(dW, gW, cb);
    uvg_mma_kernel<<<dim3(32, NSPLIT), 256>>>(x);
    scan_kernel<<<dim3(Bc, 3), 384, SCAN_SMEM>>>(db, ntl);
    out_ln_kernel<<<Mrows / 32, 512>>>(leaf, gb, gamma, beta, out);
}

// round 17
// speedup vs baseline: 1.1701x; 1.0857x over previous
#include <cuda_runtime.h>
#include <cuda_bf16.h>
#include <math.h>

// Problem constants
#define Bc   8
#define Sc   512
#define Dc   1024
#define Oc   1024
#define Tc   12
#define Lc   8
#define Mrows (Bc*Sc)          // 4096
#define NDEC 36                // T*DEP
#define NSPLIT 4               // split-K for uvg mma

typedef unsigned long long u64;
typedef unsigned int u32;

// ------------------------------------------------------------------
// Scratch (allocation-free: device globals)
// ------------------------------------------------------------------
__device__ float g_W2p[4][NDEC * Dc];       // K-split partials of W2^T
__device__ float g_bias2[NDEC];             // dW @ cb
__device__ __nv_bfloat16 g_Wh[96 * Dc];     // weight hi (bf16) [96][1024]
__device__ __nv_bfloat16 g_Wl[96 * Dc];     // weight lo (bf16)
__device__ float g_uvp[NSPLIT][Mrows * 96]; // split-K partials of uvg
__device__ float g_uvg[Mrows * 96];         // reduced uvg
__device__ float g_dec[Mrows * NDEC];       // sigmoid decision values

// ------------------------------------------------------------------
// helpers
// ------------------------------------------------------------------
__device__ __forceinline__ u64 pack2(float x, float y) {
    u64 r; asm("mov.b64 %0, {%1,%2};" : "=l"(r) : "f"(x), "f"(y)); return r;
}
__device__ __forceinline__ void unpack2(u64 v, float& x, float& y) {
    asm("mov.b64 {%0,%1}, %2;" : "=f"(x), "=f"(y) : "l"(v));
}
__device__ __forceinline__ void fma2(u64& d, u64 a, u64 b) {
    asm("fma.rn.f32x2 %0, %1, %2, %0;" : "+l"(d) : "l"(a), "l"(b));
}
__device__ __forceinline__ float softplusf(float v) {
    return (v > 20.f) ? v : log1pf(expf(v));
}
__device__ __forceinline__ u32 smem_u32(const void* p) {
    u32 a;
    asm("{ .reg .u64 t; cvta.to.shared.u64 t, %1; cvt.u32.u64 %0, t; }"
        : "=r"(a) : "l"(p));
    return a;
}
__device__ __forceinline__ void cp_async16(u32 dst_smem, const void* src) {
    asm volatile("cp.async.cg.shared.global [%0], [%1], 16;"
                 :: "r"(dst_smem), "l"(src) : "memory");
}
#define CP_COMMIT() asm volatile("cp.async.commit_group;" ::: "memory")
#define CP_WAIT0()  asm volatile("cp.async.wait_group 0;" ::: "memory")

// bf16 mma.sync (baseline PTX, works on sm_100)
__device__ __forceinline__ void mma_bf16(
    float& c0, float& c1, float& c2, float& c3,
    u32 a0, u32 a1, u32 a2, u32 a3, u32 b0, u32 b1)
{
    asm volatile(
        "mma.sync.aligned.m16n8k16.row.col.f32.bf16.bf16.f32 "
        "{%0,%1,%2,%3}, {%4,%5,%6,%7}, {%8,%9}, {%0,%1,%2,%3};"
        : "+f"(c0), "+f"(c1), "+f"(c2), "+f"(c3)
        : "r"(a0), "r"(a1), "r"(a2), "r"(a3), "r"(b0), "r"(b1));
}

__device__ __forceinline__ void bf16_split(float v, unsigned short& h, unsigned short& l) {
    __nv_bfloat16 hb = __float2bfloat16(v);
    float lo = v - __bfloat162float(hb);
    h = __bfloat16_as_ushort(hb);
    l = __bfloat16_as_ushort(__float2bfloat16(lo));
}

// ------------------------------------------------------------------
// K0a: W2^T partials.  W2p[part][tn][e] = sum_{d in part} cW[e][d]*dW[tn][d]
// ------------------------------------------------------------------
__global__ __launch_bounds__(256) void w2_partial(
    const float* __restrict__ cW, const float* __restrict__ dW)
{
    __shared__ float s_cWT[64][68];
    __shared__ float s_dW[NDEC][68];

    const int tid = threadIdx.x;
    const int e0  = blockIdx.x * 64;
    const int kb  = blockIdx.y * 256;
    const int el  = tid & 63;
    const int tg  = tid >> 6;

    float acc[9];
    #pragma unroll
    for (int j = 0; j < 9; ++j) acc[j] = 0.f;

    for (int ki = 0; ki < 4; ++ki) {
        const int k0 = kb + ki * 64;
        #pragma unroll
        for (int t = 0; t < 4; ++t) {
            int idx = tid + t * 256;
            int er = idx >> 4, cc = idx & 15;
            float4 v = *(const float4*)(cW + (size_t)(e0 + er) * Dc + k0 + cc * 4);
            s_cWT[cc * 4 + 0][er] = v.x;
            s_cWT[cc * 4 + 1][er] = v.y;
            s_cWT[cc * 4 + 2][er] = v.z;
            s_cWT[cc * 4 + 3][er] = v.w;
        }
        for (int idx = tid; idx < NDEC * 16; idx += 256) {
            int wr = idx >> 4, cc = idx & 15;
            float4 v = *(const float4*)(dW + (size_t)wr * Dc + k0 + cc * 4);
            s_dW[wr][cc * 4 + 0] = v.x;
            s_dW[wr][cc * 4 + 1] = v.y;
            s_dW[wr][cc * 4 + 2] = v.z;
            s_dW[wr][cc * 4 + 3] = v.w;
        }
        __syncthreads();

        #pragma unroll 4
        for (int kk = 0; kk < 64; ++kk) {
            float a = s_cWT[kk][el];
            #pragma unroll
            for (int j = 0; j < 9; ++j)
                acc[j] += a * s_dW[tg * 9 + j][kk];
        }
        __syncthreads();
    }

    #pragma unroll
    for (int j = 0; j < 9; ++j) {
        int tn = tg * 9 + j;
        g_W2p[blockIdx.y][(tn << 10) + e0 + el] = acc[j];
    }
}

// ------------------------------------------------------------------
// K0b (fused): blocks [0,96): bf16 hi/lo split of the 96x1024 weight
//   matrix; W2 reduction + gW transpose inline.
// blocks [96,132): bias2[tn] = dot(cb, dW[tn])
// ------------------------------------------------------------------
__global__ __launch_bounds__(256) void wsplit_kernel(
    const float* __restrict__ dW, const float* __restrict__ gW,
    const float* __restrict__ cb)
{
    const int tid = threadIdx.x;

    if (blockIdx.x < 96) {
        int lin = blockIdx.x * 256 + tid;
        int c   = lin >> 8;
        int e4  = (lin & 255) * 4;
        float w[4];
        if (c < NDEC) {
            float4 v = *(const float4*)(dW + (size_t)c * Dc + e4);
            w[0] = v.x; w[1] = v.y; w[2] = v.z; w[3] = v.w;
        } else if (c < 72) {
            size_t o = (size_t)(c - 36) * Dc + e4;
            float4 a = *(const float4*)(g_W2p[0] + o);
            float4 b = *(const float4*)(g_W2p[1] + o);
            float4 cc = *(const float4*)(g_W2p[2] + o);
            float4 d = *(const float4*)(g_W2p[3] + o);
            w[0] = (a.x + b.x) + (cc.x + d.x);
            w[1] = (a.y + b.y) + (cc.y + d.y);
            w[2] = (a.z + b.z) + (cc.z + d.z);
            w[3] = (a.w + b.w) + (cc.w + d.w);
        } else if (c < 84) {
            int t = c - 72;
            #pragma unroll
            for (int j = 0; j < 4; ++j)
                w[j] = gW[(size_t)(e4 + j) * Tc + t];
        } else {
            w[0] = w[1] = w[2] = w[3] = 0.f;
        }
        unsigned short h[4], l[4];
        #pragma unroll
        for (int j = 0; j < 4; ++j) bf16_split(w[j], h[j], l[j]);
        u64 hw = (u64)h[0] | ((u64)h[1] << 16) | ((u64)h[2] << 32) | ((u64)h[3] << 48);
        u64 lw = (u64)l[0] | ((u64)l[1] << 16) | ((u64)l[2] << 32) | ((u64)l[3] << 48);
        *(u64*)((char*)g_Wh + ((size_t)c * Dc + e4) * 2) = hw;
        *(u64*)((char*)g_Wl + ((size_t)c * Dc + e4) * 2) = lw;
    } else {
        __shared__ float red[8];
        const int tn = blockIdx.x - 96;
        float4 c4 = ((const float4*)cb)[tid];
        float4 w4 = ((const float4*)(dW + (size_t)tn * Dc))[tid];
        float p = c4.x * w4.x + c4.y * w4.y + c4.z * w4.z + c4.w * w4.w;
        #pragma unroll
        for (int off = 16; off > 0; off >>= 1) p += __shfl_xor_sync(~0u, p, off);
        if ((tid & 31) == 0) red[tid >> 5] = p;
        __syncthreads();
        if (tid == 0) {
            float s = 0.f;
            #pragma unroll
            for (int wgi = 0; wgi < 8; ++wgi) s += red[wgi];
            g_bias2[tn] = s;
        }
    }
}

// ------------------------------------------------------------------
// K2: uvg = x @ W^T via mma.sync bf16 hi/lo (3 terms).
// grid (32 Mtiles, 4 Ksplit), 256 threads (8 warps = 4M x 2N).
// ------------------------------------------------------------------
#define XW 20   // padded words per row

__global__ __launch_bounds__(256) void uvg_mma_kernel(const float* __restrict__ x)
{
    __shared__ u32 sXh[128][XW];
    __shared__ u32 sXl[128][XW];
    __shared__ u32 sWh[96][XW];
    __shared__ u32 sWl[96][XW];

    const int tid   = threadIdx.x;
    const int wid   = tid >> 5;
    const int lane  = tid & 31;
    const int row0  = blockIdx.x * 128;
    const int kbase = blockIdx.y * 256;

    const int wm = wid & 3;
    const int wn = wid >> 2;
    const int mbase = wm * 32;
    const int nbase = wn * 48;
    const int r  = lane >> 2;
    const int cq = lane & 3;

    float acc[2][6][4];
    #pragma unroll
    for (int mt = 0; mt < 2; ++mt)
        #pragma unroll
        for (int nt = 0; nt < 6; ++nt)
            #pragma unroll
            for (int e = 0; e < 4; ++e) acc[mt][nt][e] = 0.f;

    const int xk4  = tid & 7;
    const int wseg = tid & 7;

    float4 xv[4];
    uint2 wvh[3], wvl[3];

    {
        const int k0 = kbase;
        #pragma unroll
        for (int t = 0; t < 4; ++t) {
            int m = (tid + t * 256) >> 3;
            xv[t] = *(const float4*)(x + (size_t)(row0 + m) * Dc + k0 + xk4 * 4);
        }
        #pragma unroll
        for (int t = 0; t < 3; ++t) {
            int n = (tid + t * 256) >> 3;
            wvh[t] = *(const uint2*)((const char*)g_Wh + (size_t)n * 2048 + k0 * 2 + wseg * 8);
            wvl[t] = *(const uint2*)((const char*)g_Wl + (size_t)n * 2048 + k0 * 2 + wseg * 8);
        }
    }

    for (int ch = 0; ch < 8; ++ch) {
        #pragma unroll
        for (int t = 0; t < 4; ++t) {
            int m = (tid + t * 256) >> 3;
            float v[4] = {xv[t].x, xv[t].y, xv[t].z, xv[t].w};
            unsigned short h[4], l[4];
            #pragma unroll
            for (int e = 0; e < 4; ++e) bf16_split(v[e], h[e], l[e]);
            sXh[m][xk4 * 2 + 0] = ((u32)h[1] << 16) | h[0];
            sXh[m][xk4 * 2 + 1] = ((u32)h[3] << 16) | h[2];
            sXl[m][xk4 * 2 + 0] = ((u32)l[1] << 16) | l[0];
            sXl[m][xk4 * 2 + 1] = ((u32)l[3] << 16) | l[2];
        }
        #pragma unroll
        for (int t = 0; t < 3; ++t) {
            int n = (tid + t * 256) >> 3;
            sWh[n][wseg * 2 + 0] = wvh[t].x;
            sWh[n][wseg * 2 + 1] = wvh[t].y;
            sWl[n][wseg * 2 + 0] = wvl[t].x;
            sWl[n][wseg * 2 + 1] = wvl[t].y;
        }
        __syncthreads();

        if (ch < 7) {
            const int k0 = kbase + (ch + 1) * 32;
            #pragma unroll
            for (int t = 0; t < 4; ++t) {
                int m = (tid + t * 256) >> 3;
                xv[t] = *(const float4*)(x + (size_t)(row0 + m) * Dc + k0 + xk4 * 4);
            }
            #pragma unroll
            for (int t = 0; t < 3; ++t) {
                int n = (tid + t * 256) >> 3;
                wvh[t] = *(const uint2*)((const char*)g_Wh + (size_t)n * 2048 + k0 * 2 + wseg * 8);
                wvl[t] = *(const uint2*)((const char*)g_Wl + (size_t)n * 2048 + k0 * 2 + wseg * 8);
            }
        }

        #pragma unroll
        for (int kg = 0; kg < 2; ++kg) {
            const int wb = kg * 8;
            u32 ah[2][4], al[2][4];
            #pragma unroll
            for (int mt = 0; mt < 2; ++mt) {
                const int ra = mbase + mt * 16 + r;
                ah[mt][0] = sXh[ra][wb + cq];
                ah[mt][1] = sXh[ra + 8][wb + cq];
                ah[mt][2] = sXh[ra][wb + cq + 4];
                ah[mt][3] = sXh[ra + 8][wb + cq + 4];
                al[mt][0] = sXl[ra][wb + cq];
                al[mt][1] = sXl[ra + 8][wb + cq];
                al[mt][2] = sXl[ra][wb + cq + 4];
                al[mt][3] = sXl[ra + 8][wb + cq + 4];
            }
            u32 bh[6][2], bl[6][2];
            #pragma unroll
            for (int nt = 0; nt < 6; ++nt) {
                const int n = nbase + nt * 8 + r;
                bh[nt][0] = sWh[n][wb + cq];
                bh[nt][1] = sWh[n][wb + cq + 4];
                bl[nt][0] = sWl[n][wb + cq];
                bl[nt][1] = sWl[n][wb + cq + 4];
            }
            #pragma unroll
            for (int mt = 0; mt < 2; ++mt)
                #pragma unroll
                for (int nt = 0; nt < 6; ++nt) {
                    float* c = acc[mt][nt];
                    mma_bf16(c[0], c[1], c[2], c[3],
                             ah[mt][0], ah[mt][1], ah[mt][2], ah[mt][3],
                             bh[nt][0], bh[nt][1]);
                    mma_bf16(c[0], c[1], c[2], c[3],
                             ah[mt][0], ah[mt][1], ah[mt][2], ah[mt][3],
                             bl[nt][0], bl[nt][1]);
                    mma_bf16(c[0], c[1], c[2], c[3],
                             al[mt][0], al[mt][1], al[mt][2], al[mt][3],
                             bh[nt][0], bh[nt][1]);
                }
        }
        __syncthreads();
    }

    float* dst = g_uvp[blockIdx.y];
    #pragma unroll
    for (int mt = 0; mt < 2; ++mt) {
        const int m = row0 + mbase + mt * 16;
        #pragma unroll
        for (int nt = 0; nt < 6; ++nt) {
            const int n = nbase + nt * 8 + cq * 2;
            *(float2*)(dst + (size_t)(m + r) * 96 + n)     = make_float2(acc[mt][nt][0], acc[mt][nt][1]);
            *(float2*)(dst + (size_t)(m + r + 8) * 96 + n) = make_float2(acc[mt][nt][2], acc[mt][nt][3]);
        }
    }
}

// ------------------------------------------------------------------
// K2b: reduce split-K partials (float4-wide, 384 blocks = full chip)
// Same (s0+s1)+(s2+s3) order as the old sum4 -> bit-identical values.
// ------------------------------------------------------------------
__global__ __launch_bounds__(256) void uvg_reduce()
{
    int i = blockIdx.x * 256 + threadIdx.x;   // float4 index, < 98304
    float4 a = ((const float4*)g_uvp[0])[i];
    float4 b = ((const float4*)g_uvp[1])[i];
    float4 c = ((const float4*)g_uvp[2])[i];
    float4 d = ((const float4*)g_uvp[3])[i];
    float4 s;
    s.x = (a.x + b.x) + (c.x + d.x);
    s.y = (a.y + b.y) + (c.y + d.y);
    s.z = (a.z + b.z) + (c.z + d.z);
    s.w = (a.w + b.w) + (c.w + d.w);
    ((float4*)g_uvg)[i] = s;
}

// ------------------------------------------------------------------
// K3: per-(b,tn) causal scan of u -> sigmoid decision values.
// grid (8 b, 3 tn-groups of 12), 384 threads = 12 tn x 32 chunks of 16.
// cp.async stages u/v slices from the REDUCED g_uvg (3072 copies/block,
// 8/thread -- the 4-split version was LSU-issue bound at 12288 copies).
// dyn smem: sU[6144] | sV[6144] | spw[512] | part[384] = 51.5 KB
// ------------------------------------------------------------------
#define SCAN_SMEM   ((6144 + 6144 + Sc + 384) * 4)

__global__ __launch_bounds__(384) void scan_kernel(
    const float* __restrict__ db, const float* __restrict__ ntl)
{
    extern __shared__ __align__(16) float dsm[];
    float* sU   = dsm;                          // [Sc][12]
    float* sV   = dsm + 6144;                   // [Sc][12]
    float* spw  = dsm + 12288;                  // [Sc]
    float* part = dsm + 12288 + Sc;             // [32][12]

    const int tid = threadIdx.x;
    const int b   = blockIdx.x;
    const int tn0 = blockIdx.y * 12;
    const u32 smem_base = smem_u32(dsm);

    // issue cp.async copies: 3072 x 16B, 8 per thread
    #pragma unroll
    for (int it = 0; it < 8; ++it) {
        int cid = tid + it * 384;               // < 3072
        int s = cid / 6;
        int j = cid - s * 6;
        const float* src;
        int dstf;
        if (j < 3) {
            src  = g_uvg + (size_t)(b * Sc + s) * 96 + 36 + tn0 + j * 4;
            dstf = s * 12 + j * 4;
        } else {
            src  = g_uvg + (size_t)(b * Sc + s) * 96 + tn0 + (j - 3) * 4;
            dstf = 6144 + s * 12 + (j - 3) * 4;
        }
        cp_async16(smem_base + dstf * 4, src);
    }
    CP_COMMIT();

    // overlap: powers table (fp32)
    const float L2D = -0.15200309344504997f;    // log2(0.9)
    for (int i = tid; i < Sc; i += 384)
        spw[i] = exp2f((float)i * L2D);

    CP_WAIT0();
    __syncthreads();

    const int tl = tid % 12;           // local tn
    const int ch = tid / 12;           // 0..31
    const int s0 = ch * 16;
    const int tn = tn0 + tl;

    // pass 1: chunk partial sums of y_s = 0.9^s * u[b,s-1,tn]
    {
        float sum = 0.f;
        #pragma unroll
        for (int i = 0; i < 16; ++i) {
            int s = s0 + i;
            if (s >= 1) sum += sU[(s - 1) * 12 + tl] * spw[s];
        }
        part[ch * 12 + tl] = sum;
    }
    __syncthreads();

    if (tid < 12) {
        float run = 0.f;
        #pragma unroll
        for (int cch = 0; cch < 32; ++cch) {
            float t = part[cch * 12 + tid];
            part[cch * 12 + tid] = run;
            run += t;
        }
    }
    __syncthreads();

    // pass 2: emit sigmoid(z)
    {
        const float invT = 1.f / softplusf(ntl[tn] + 0.5413f);
        const float bias = db[tn] + g_bias2[tn];
        float C = part[ch * 12 + tl];
        #pragma unroll
        for (int i = 0; i < 16; ++i) {
            int s = s0 + i;
            int row = b * Sc + s;
            float pw = spw[s];
            if (s >= 1) C += sU[(s - 1) * 12 + tl] * pw;
            float recip = 1.0f / (pw + 1e-8f);
            float decE  = 0.1f * C * recip;
            float z     = (sV[s * 12 + tl] + decE + bias) * invT;
            g_dec[(size_t)row * NDEC + tn] = 1.f / (1.f + expf(-z));
        }
    }
}

// ------------------------------------------------------------------
// K5: fused q-construction + out = q @ leaf + LayerNorm
// 32 rows/block, 512 threads (2 cols each), 128 blocks; f32x2 FMAs.
// ------------------------------------------------------------------
__global__ __launch_bounds__(512) void out_ln_kernel(
    const float* __restrict__ leaf,
    const float* __restrict__ gb,
    const float* __restrict__ gamma,
    const float* __restrict__ beta,
    float* __restrict__ out)
{
    __shared__ __align__(16) float sQT[96][32];
    __shared__ float sRed[32][16][2];
    __shared__ float sMu[32], sRstd[32];

    const int tid  = threadIdx.x;
    const int row0 = blockIdx.x * 32;

    // phase 0: 384 threads, one per (row, tree)
    if (tid < 384) {
        const int row_l = tid / Tc;        // 0..31
        const int t     = tid % Tc;        // 0..11
        const int row   = row0 + row_l;

        float g[Tc];
        float mx = -1e30f;
        #pragma unroll
        for (int tt = 0; tt < Tc; ++tt) {
            g[tt] = g_uvg[(size_t)row * 96 + 72 + tt] + gb[tt];
            mx = fmaxf(mx, g[tt]);
        }
        float sum = 0.f;
        #pragma unroll
        for (int tt = 0; tt < Tc; ++tt) { g[tt] = expf(g[tt] - mx); sum += g[tt]; }
        const float wt = g[t] / sum;

        const float d0 = g_dec[(size_t)row * NDEC + t * 3 + 0];
        const float d1 = g_dec[(size_t)row * NDEC + t * 3 + 1];
        const float d2 = g_dec[(size_t)row * NDEC + t * 3 + 2];
        #pragma unroll
        for (int l = 0; l < Lc; ++l) {
            float p = ((l & 4) ? (1.f - d0) : d0)
                    * ((l & 2) ? (1.f - d1) : d1)
                    * ((l & 1) ? (1.f - d2) : d2);
            sQT[t * 8 + l][row_l] = wt * p;
        }
    }
    __syncthreads();

    // GEMM: 32 rows x 2 cols per thread, f32x2 over row pairs
    const float2* leaf2 = (const float2*)leaf;
    u64 acc2[16][2];
    #pragma unroll
    for (int j = 0; j < 16; ++j) { acc2[j][0] = 0ull; acc2[j][1] = 0ull; }

    #pragma unroll 2
    for (int i = 0; i < 96; ++i) {
        float2 lf = leaf2[(size_t)i * 512 + tid];
        u64 lx = pack2(lf.x, lf.x);
        u64 ly = pack2(lf.y, lf.y);
        const ulonglong2* qp2 = (const ulonglong2*)&sQT[i][0];
        #pragma unroll
        for (int jj = 0; jj < 8; ++jj) {
            ulonglong2 qq = qp2[jj];
            fma2(acc2[2 * jj + 0][0], qq.x, lx);
            fma2(acc2[2 * jj + 0][1], qq.x, ly);
            fma2(acc2[2 * jj + 1][0], qq.y, lx);
            fma2(acc2[2 * jj + 1][1], qq.y, ly);
        }
    }

    float acc[32][2];
    #pragma unroll
    for (int j = 0; j < 16; ++j) {
        unpack2(acc2[j][0], acc[2 * j][0], acc[2 * j + 1][0]);
        unpack2(acc2[j][1], acc[2 * j][1], acc[2 * j + 1][1]);
    }

    const int wid  = tid >> 5;
    const int lane = tid & 31;
    #pragma unroll
    for (int r = 0; r < 32; ++r) {
        float s  = acc[r][0] + acc[r][1];
        float sq = acc[r][0] * acc[r][0] + acc[r][1] * acc[r][1];
        #pragma unroll
        for (int off = 16; off > 0; off >>= 1) {
            s  += __shfl_xor_sync(~0u, s,  off);
            sq += __shfl_xor_sync(~0u, sq, off);
        }
        if (lane == 0) { sRed[r][wid][0] = s; sRed[r][wid][1] = sq; }
    }
    __syncthreads();

    // each warp reduces 2 rows across the 16 warps
    {
        #pragma unroll
        for (int rr = 0; rr < 2; ++rr) {
            int r = wid * 2 + rr;
            float s  = (lane < 16) ? sRed[r][lane][0] : 0.f;
            float sq = (lane < 16) ? sRed[r][lane][1] : 0.f;
            #pragma unroll
            for (int off = 8; off > 0; off >>= 1) {
                s  += __shfl_xor_sync(~0u, s,  off);
                sq += __shfl_xor_sync(~0u, sq, off);
            }
            if (lane == 0) {
                float mu  = s * (1.f / Oc);
                float var = sq * (1.f / Oc) - mu * mu;
                sMu[r]   = mu;
                sRstd[r] = rsqrtf(var + 1e-5f);
            }
        }
    }
    __syncthreads();

    const float2 g2 = ((const float2*)gamma)[tid];
    const float2 b2 = ((const float2*)beta)[tid];
    float2* out2 = (float2*)out;
    #pragma unroll
    for (int r = 0; r < 32; ++r) {
        float mu = sMu[r], rstd = sRstd[r];
        float2 o;
        o.x = (acc[r][0] - mu) * rstd * g2.x + b2.x;
        o.y = (acc[r][1] - mu) * rstd * g2.y + b2.y;
        out2[(size_t)(row0 + r) * 512 + tid] = o;
    }
}

// ------------------------------------------------------------------
// launch
// ------------------------------------------------------------------
extern "C" void kernel_launch(void* const* d_in, const int* in_sizes, int n_in,
                              void* d_out, int out_size)
{
    const float* x     = (const float*)d_in[0];
    const float* cW    = (const float*)d_in[1];
    const float* cb    = (const float*)d_in[2];
    const float* dW    = (const float*)d_in[3];
    const float* db    = (const float*)d_in[4];
    const float* leaf  = (const float*)d_in[5];
    const float* gW    = (const float*)d_in[6];
    const float* gb    = (const float*)d_in[7];
    const float* ntl   = (const float*)d_in[8];
    const float* gamma = (const float*)d_in[9];
    const float* beta  = (const float*)d_in[10];
    float* out = (float*)d_out;

    static bool attr_done = false;
    if (!attr_done) {
        cudaFuncSetAttribute(scan_kernel,
                             cudaFuncAttributeMaxDynamicSharedMemorySize, SCAN_SMEM);
        attr_done = true;
    }

    w2_partial<<<dim3(16, 4), 256>>>(cW, dW);
    wsplit_kernel<<<96 + NDEC, 256>>>(dW, gW, cb);
    uvg_mma_kernel<<<dim3(32, NSPLIT), 256>>>(x);
    uvg_reduce<<<384, 256>>>();
    scan_kernel<<<dim3(Bc, 3), 384, SCAN_SMEM>>>(db, ntl);
    out_ln_kernel<<<Mrows / 32, 512>>>(leaf, gb, gamma, beta, out);
}